// round 2
// baseline (speedup 1.0000x reference)
#include <cuda_runtime.h>
#include <math.h>

// Shapes
// x:  [32, 112, 112, 128] fp32  -> B=32, HW=12544, C=128
// w1: [128, 2048], b1: [2048], w2: [2048, 128], b2: [128]
#define B      32
#define HW     12544
#define C      128
#define R      2048
#define NSPLIT 98              // 12544 / 128 rows per split
#define ROWS_PER_SPLIT 128
#define F4_PER_B  (HW * C / 4)         // 401408 float4 per batch
#define F4_PER_BLK (ROWS_PER_SPLIT * C / 4)  // 4096 float4 per block

// Scratch (device globals: allocation-free)
__device__ __align__(16) float g_partial[B * NSPLIT * C]; // 1.6 MB
__device__ __align__(16) float g_gate[B * C];             // 16 KB

// ---------------------------------------------------------------------------
// Kernel 1: partial pooling sums.  grid (NSPLIT, B), 256 threads.
// Thread t's float4 lane index within a row-chunk is t + i*256; since
// 256 % 32 == 0, the channel-group (lane % 32) is FIXED per thread, so each
// thread accumulates one float4 of 4 channels across its rows.
// ---------------------------------------------------------------------------
__global__ __launch_bounds__(256, 8)
void se_pool_kernel(const float* __restrict__ x) {
    const int b = blockIdx.y;
    const int split = blockIdx.x;
    const float4* __restrict__ xb =
        reinterpret_cast<const float4*>(x) + (size_t)b * F4_PER_B + (size_t)split * F4_PER_BLK;
    const int t = threadIdx.x;

    float4 acc = make_float4(0.f, 0.f, 0.f, 0.f);
#pragma unroll
    for (int i = 0; i < 16; i++) {           // 16 * 256 = 4096 float4
        float4 v = xb[t + i * 256];
        acc.x += v.x; acc.y += v.y; acc.z += v.z; acc.w += v.w;
    }

    __shared__ float4 sh[256];
    sh[t] = acc;
    __syncthreads();

    if (t < 32) {
        float4 s = sh[t];
#pragma unroll
        for (int j = 1; j < 8; j++) {
            float4 v = sh[t + j * 32];
            s.x += v.x; s.y += v.y; s.z += v.z; s.w += v.w;
        }
        // channels [4t .. 4t+3] of this (b, split)
        reinterpret_cast<float4*>(g_partial)[(size_t)(b * NSPLIT + split) * 32 + t] = s;
    }
}

// ---------------------------------------------------------------------------
// Kernel 2: excite.  grid (B), 256 threads. Reduce partials -> s[128],
// GEMM1 (+tanh-approx GELU) -> h[2048] in smem, GEMM2 (+sigmoid) -> g_gate.
// ---------------------------------------------------------------------------
__global__ __launch_bounds__(256, 1)
void se_excite_kernel(const float* __restrict__ w1, const float* __restrict__ b1,
                      const float* __restrict__ w2, const float* __restrict__ b2) {
    const int b = blockIdx.x;
    const int t = threadIdx.x;

    __shared__ float s[C];
    __shared__ float h[R];

    // reduce partial sums -> mean
    if (t < C) {
        const float* p = g_partial + (size_t)b * NSPLIT * C + t;
        float acc = 0.f;
#pragma unroll 7
        for (int k = 0; k < NSPLIT; k++) acc += p[(size_t)k * C];
        s[t] = acc * (1.0f / (float)HW);
    }
    __syncthreads();

    // GEMM1: h[r] = gelu(dot(s, w1[:, r]) + b1[r]); each thread does 8 r's
#pragma unroll
    for (int rr = 0; rr < 8; rr++) {
        const int r = t + rr * 256;
        float acc = b1[r];
#pragma unroll 8
        for (int c = 0; c < C; c++) acc += s[c] * w1[(size_t)c * R + r];
        // tanh-approx GELU (jax.nn.gelu default)
        float u = acc;
        float inner = 0.7978845608028654f * (u + 0.044715f * u * u * u);
        h[r] = 0.5f * u * (1.0f + tanhf(inner));
    }
    __syncthreads();

    // GEMM2: g[c] = sigmoid(dot(h, w2[:, c]) + b2[c]); threads 0..127
    if (t < C) {
        float acc = b2[t];
#pragma unroll 8
        for (int r = 0; r < R; r++) acc += h[r] * w2[(size_t)r * C + t];
        g_gate[b * C + t] = 1.0f / (1.0f + expf(-acc));
    }
}

// ---------------------------------------------------------------------------
// Kernel 3: scale.  grid (NSPLIT, B), 256 threads, float4 streaming.
// Channel group per thread is fixed (same argument as pool), so the 4 gate
// values live in registers for the whole block.
// ---------------------------------------------------------------------------
__global__ __launch_bounds__(256, 8)
void se_scale_kernel(const float* __restrict__ x, float* __restrict__ out) {
    const int b = blockIdx.y;
    const int blk = blockIdx.x;
    const size_t base = (size_t)b * F4_PER_B + (size_t)blk * F4_PER_BLK;
    const float4* __restrict__ xi = reinterpret_cast<const float4*>(x) + base;
    float4* __restrict__ xo = reinterpret_cast<float4*>(out) + base;
    const int t = threadIdx.x;

    const int c4 = (t * 4) & (C - 1);   // channel of lane .x (fixed per thread)
    const float4 g4 = *reinterpret_cast<const float4*>(g_gate + b * C + c4);

#pragma unroll
    for (int i = 0; i < 16; i++) {
        float4 v = xi[t + i * 256];
        v.x *= g4.x; v.y *= g4.y; v.z *= g4.z; v.w *= g4.w;
        xo[t + i * 256] = v;
    }
}

extern "C" void kernel_launch(void* const* d_in, const int* in_sizes, int n_in,
                              void* d_out, int out_size) {
    const float* x  = (const float*)d_in[0];
    const float* w1 = (const float*)d_in[1];
    const float* b1 = (const float*)d_in[2];
    const float* w2 = (const float*)d_in[3];
    const float* b2 = (const float*)d_in[4];
    float* out = (float*)d_out;

    dim3 grid(NSPLIT, B);
    se_pool_kernel<<<grid, 256>>>(x);
    se_excite_kernel<<<B, 256>>>(w1, b1, w2, b2);
    se_scale_kernel<<<grid, 256>>>(x, out);
}

// round 3
// speedup vs baseline: 2.2552x; 2.2552x over previous
#include <cuda_runtime.h>
#include <math.h>

// Shapes
// x:  [32, 112, 112, 128] fp32  -> B=32, HW=12544, C=128
// w1: [128, 2048], b1: [2048], w2: [2048, 128], b2: [128]
#define B      32
#define HW     12544
#define C      128
#define R      2048
#define NSPLIT 98              // 12544 / 128 rows per split
#define ROWS_PER_SPLIT 128
#define F4_PER_B  (HW * C / 4)               // 401408 float4 per batch
#define F4_PER_BLK (ROWS_PER_SPLIT * C / 4)  // 4096 float4 per block

// Scratch (device globals: allocation-free)
__device__ __align__(16) float g_partial[B * NSPLIT * C]; // 1.6 MB
__device__ __align__(16) float g_s[B * C];                // pooled means, 16 KB
__device__ __align__(16) float g_h[B * R];                // GELU activations, 256 KB
__device__ __align__(16) float g_gate[B * C];             // 16 KB

// ---------------------------------------------------------------------------
// Kernel 1: partial pooling sums.  grid (NSPLIT, B), 256 threads.
// Channel group per thread is fixed (256 % 32 == 0), so each thread
// accumulates one float4 of 4 channels across its rows.
// ---------------------------------------------------------------------------
__global__ __launch_bounds__(256, 8)
void se_pool_kernel(const float* __restrict__ x) {
    const int b = blockIdx.y;
    const int split = blockIdx.x;
    const float4* __restrict__ xb =
        reinterpret_cast<const float4*>(x) + (size_t)b * F4_PER_B + (size_t)split * F4_PER_BLK;
    const int t = threadIdx.x;

    float4 acc = make_float4(0.f, 0.f, 0.f, 0.f);
#pragma unroll
    for (int i = 0; i < 16; i++) {           // 16 * 256 = 4096 float4
        float4 v = xb[t + i * 256];
        acc.x += v.x; acc.y += v.y; acc.z += v.z; acc.w += v.w;
    }

    __shared__ float4 sh[256];
    sh[t] = acc;
    __syncthreads();

    if (t < 32) {
        float4 s = sh[t];
#pragma unroll
        for (int j = 1; j < 8; j++) {
            float4 v = sh[t + j * 32];
            s.x += v.x; s.y += v.y; s.z += v.z; s.w += v.w;
        }
        reinterpret_cast<float4*>(g_partial)[(size_t)(b * NSPLIT + split) * 32 + t] = s;
    }
}

// ---------------------------------------------------------------------------
// Kernel 2a: reduce partials -> mean s[B][C].  grid (B), 128 threads.
// ---------------------------------------------------------------------------
__global__ __launch_bounds__(128, 8)
void se_reduce_kernel() {
    const int b = blockIdx.x;
    const int t = threadIdx.x;
    const float* p = g_partial + (size_t)b * NSPLIT * C + t;
    float acc = 0.f;
#pragma unroll 14
    for (int k = 0; k < NSPLIT; k++) acc += p[(size_t)k * C];
    g_s[b * C + t] = acc * (1.0f / (float)HW);
}

// ---------------------------------------------------------------------------
// Kernel 2b: GEMM1 + tanh-GELU.  grid (R/128 = 16, B), 128 threads.
// Each thread computes one r.  w1 column loads are coalesced (consecutive r).
// ---------------------------------------------------------------------------
__global__ __launch_bounds__(128, 8)
void se_gemm1_kernel(const float* __restrict__ w1, const float* __restrict__ b1) {
    const int b = blockIdx.y;
    const int r = blockIdx.x * 128 + threadIdx.x;
    const int t = threadIdx.x;

    __shared__ float s[C];
    s[t] = g_s[b * C + t];
    __syncthreads();

    float acc = b1[r];
#pragma unroll 16
    for (int c = 0; c < C; c++) acc += s[c] * w1[(size_t)c * R + r];

    // tanh-approx GELU (jax.nn.gelu default)
    float u = acc;
    float inner = 0.7978845608028654f * (u + 0.044715f * u * u * u);
    g_h[(size_t)b * R + r] = 0.5f * u * (1.0f + tanhf(inner));
}

// ---------------------------------------------------------------------------
// Kernel 2c: GEMM2 + sigmoid, split-K.  grid (B), 1024 threads.
// Thread (slice = t/128, c = t%128): partial dot over 256 r's, shared reduce.
// w2 loads coalesced (consecutive c within a slice-row).
// ---------------------------------------------------------------------------
__global__ __launch_bounds__(1024, 1)
void se_gemm2_kernel(const float* __restrict__ w2, const float* __restrict__ b2) {
    const int b = blockIdx.x;
    const int t = threadIdx.x;
    const int c = t & (C - 1);
    const int slice = t >> 7;          // 0..7, each covers 256 r's

    __shared__ float h[R];
    __shared__ float red[1024];

    // load h[b] into shared: 2048 floats / 1024 threads = 2 each
    h[t]        = g_h[(size_t)b * R + t];
    h[t + 1024] = g_h[(size_t)b * R + t + 1024];
    __syncthreads();

    const int r0 = slice * 256;
    float acc = 0.f;
#pragma unroll 16
    for (int r = 0; r < 256; r++)
        acc += h[r0 + r] * w2[(size_t)(r0 + r) * C + c];

    red[t] = acc;
    __syncthreads();

    if (t < C) {
        float a = red[t] + b2[t];
#pragma unroll
        for (int j = 1; j < 8; j++) a += red[t + j * 128];
        g_gate[b * C + t] = 1.0f / (1.0f + expf(-a));
    }
}

// ---------------------------------------------------------------------------
// Kernel 3: scale.  grid (NSPLIT, B), 256 threads, float4 streaming.
// ---------------------------------------------------------------------------
__global__ __launch_bounds__(256, 8)
void se_scale_kernel(const float* __restrict__ x, float* __restrict__ out) {
    const int b = blockIdx.y;
    const int blk = blockIdx.x;
    const size_t base = (size_t)b * F4_PER_B + (size_t)blk * F4_PER_BLK;
    const float4* __restrict__ xi = reinterpret_cast<const float4*>(x) + base;
    float4* __restrict__ xo = reinterpret_cast<float4*>(out) + base;
    const int t = threadIdx.x;

    const int c4 = (t * 4) & (C - 1);   // channel of lane .x (fixed per thread)
    const float4 g4 = *reinterpret_cast<const float4*>(g_gate + b * C + c4);

#pragma unroll
    for (int i = 0; i < 16; i++) {
        float4 v = xi[t + i * 256];
        v.x *= g4.x; v.y *= g4.y; v.z *= g4.z; v.w *= g4.w;
        xo[t + i * 256] = v;
    }
}

extern "C" void kernel_launch(void* const* d_in, const int* in_sizes, int n_in,
                              void* d_out, int out_size) {
    const float* x  = (const float*)d_in[0];
    const float* w1 = (const float*)d_in[1];
    const float* b1 = (const float*)d_in[2];
    const float* w2 = (const float*)d_in[3];
    const float* b2 = (const float*)d_in[4];
    float* out = (float*)d_out;

    dim3 grid(NSPLIT, B);
    se_pool_kernel<<<grid, 256>>>(x);
    se_reduce_kernel<<<B, 128>>>();
    se_gemm1_kernel<<<dim3(R / 128, B), 128>>>(w1, b1);
    se_gemm2_kernel<<<B, 1024>>>(w2, b2);
    se_scale_kernel<<<grid, 256>>>(x, out);
}

// round 4
// speedup vs baseline: 2.4922x; 1.1051x over previous
#include <cuda_runtime.h>
#include <math.h>

// Shapes
// x:  [32, 112, 112, 128] fp32  -> B=32, HW=12544, C=128
// w1: [128, 2048], b1: [2048], w2: [2048, 128], b2: [128]
#define B      32
#define HW     12544
#define C      128
#define R      2048
#define NSPLIT 98
#define ROWS_PER_SPLIT 128
#define F4_PER_B  (HW * C / 4)               // 401408 float4 per batch
#define F4_PER_BLK (ROWS_PER_SPLIT * C / 4)  // 4096 float4 per block
#define KSLICES 8                            // split-K factor for GEMM2

// Scratch (device globals: allocation-free)
__device__ __align__(16) float g_partial[B * NSPLIT * C];   // 1.6 MB pool partials
__device__ __align__(16) float g_h[B * R];                  // GELU activations
__device__ __align__(16) float g_gp[B * KSLICES * C];       // GEMM2 split-K partials

// ---------------------------------------------------------------------------
// Kernel 1: partial pooling sums.  grid (NSPLIT, B), 256 threads.
// Channel group per thread is fixed (256 % 32 == 0), so each thread
// accumulates one float4 of 4 channels across its rows.
// ---------------------------------------------------------------------------
__global__ __launch_bounds__(256, 8)
void se_pool_kernel(const float* __restrict__ x) {
    const int b = blockIdx.y;
    const int split = blockIdx.x;
    const float4* __restrict__ xb =
        reinterpret_cast<const float4*>(x) + (size_t)b * F4_PER_B + (size_t)split * F4_PER_BLK;
    const int t = threadIdx.x;

    float4 acc = make_float4(0.f, 0.f, 0.f, 0.f);
#pragma unroll
    for (int i = 0; i < 16; i++) {           // 16 * 256 = 4096 float4
        float4 v = xb[t + i * 256];
        acc.x += v.x; acc.y += v.y; acc.z += v.z; acc.w += v.w;
    }

    __shared__ float4 sh[256];
    sh[t] = acc;
    __syncthreads();

    if (t < 32) {
        float4 s = sh[t];
#pragma unroll
        for (int j = 1; j < 8; j++) {
            float4 v = sh[t + j * 32];
            s.x += v.x; s.y += v.y; s.z += v.z; s.w += v.w;
        }
        reinterpret_cast<float4*>(g_partial)[(size_t)(b * NSPLIT + split) * 32 + t] = s;
    }
}

// ---------------------------------------------------------------------------
// Kernel 2: fused reduce + GEMM1 + tanh-GELU.  grid (R/128 = 16, B), 128 thr.
// Each block redundantly reduces its batch's pool partials (50 KB, L2-hit)
// into s[128], then each thread computes one r of h.
// ---------------------------------------------------------------------------
__global__ __launch_bounds__(128, 8)
void se_gemm1_kernel(const float* __restrict__ w1, const float* __restrict__ b1) {
    const int b = blockIdx.y;
    const int r = blockIdx.x * 128 + threadIdx.x;
    const int t = threadIdx.x;

    __shared__ float s[C];
    {
        const float* p = g_partial + (size_t)b * NSPLIT * C + t;
        float acc = 0.f;
#pragma unroll 14
        for (int k = 0; k < NSPLIT; k++) acc += p[(size_t)k * C];
        s[t] = acc * (1.0f / (float)HW);
    }
    __syncthreads();

    float acc = b1[r];
#pragma unroll 16
    for (int c = 0; c < C; c++) acc += s[c] * w1[(size_t)c * R + r];

    // tanh-approx GELU (jax.nn.gelu default)
    float u = acc;
    float inner = 0.7978845608028654f * (u + 0.044715f * u * u * u);
    g_h[(size_t)b * R + r] = 0.5f * u * (1.0f + tanhf(inner));
}

// ---------------------------------------------------------------------------
// Kernel 3: GEMM2 split-K partials.  grid (KSLICES, B), 128 threads.
// Block (j, b): partial dot over r in [j*256, j*256+256) for all 128 c's.
// w2 loads coalesced across c.  Finalize (sum + sigmoid) happens in scale.
// ---------------------------------------------------------------------------
__global__ __launch_bounds__(128, 8)
void se_gemm2_kernel(const float* __restrict__ w2) {
    const int b = blockIdx.y;
    const int j = blockIdx.x;
    const int t = threadIdx.x;           // channel c

    __shared__ float hs[R / KSLICES];    // 256 floats
    {
        const float2 v = reinterpret_cast<const float2*>(g_h + (size_t)b * R + j * (R / KSLICES))[t];
        hs[2 * t]     = v.x;
        hs[2 * t + 1] = v.y;
    }
    __syncthreads();

    const float* w2s = w2 + (size_t)j * (R / KSLICES) * C + t;
    float acc = 0.f;
#pragma unroll 16
    for (int r = 0; r < R / KSLICES; r++)
        acc += hs[r] * w2s[(size_t)r * C];

    g_gp[((size_t)b * KSLICES + j) * C + t] = acc;
}

// ---------------------------------------------------------------------------
// Kernel 4: scale with fused GEMM2 finalize.  grid (NSPLIT*B), 256 threads.
// Traverses x in REVERSE of pool order so pool's L2-resident tail is hit.
// Output uses streaming stores to avoid evicting that tail.
// ---------------------------------------------------------------------------
__global__ __launch_bounds__(256, 8)
void se_scale_kernel(const float* __restrict__ x, const float* __restrict__ b2,
                     float* __restrict__ out) {
    const int rid = (B * NSPLIT - 1) - blockIdx.x;   // reversed traversal
    const int b   = rid / NSPLIT;
    const int blk = rid % NSPLIT;
    const int t = threadIdx.x;

    // gate for this thread's fixed 4-channel group
    const int c4 = (t * 4) & (C - 1);
    float4 g4;
    {
        float4 a = *reinterpret_cast<const float4*>(b2 + c4);
#pragma unroll
        for (int j = 0; j < KSLICES; j++) {
            float4 p = *reinterpret_cast<const float4*>(g_gp + ((size_t)b * KSLICES + j) * C + c4);
            a.x += p.x; a.y += p.y; a.z += p.z; a.w += p.w;
        }
        g4.x = 1.0f / (1.0f + __expf(-a.x));
        g4.y = 1.0f / (1.0f + __expf(-a.y));
        g4.z = 1.0f / (1.0f + __expf(-a.z));
        g4.w = 1.0f / (1.0f + __expf(-a.w));
    }

    const size_t base = (size_t)b * F4_PER_B + (size_t)blk * F4_PER_BLK;
    const float4* __restrict__ xi = reinterpret_cast<const float4*>(x) + base;
    float4* __restrict__ xo = reinterpret_cast<float4*>(out) + base;

#pragma unroll
    for (int i = 0; i < 16; i++) {
        float4 v = xi[t + i * 256];
        v.x *= g4.x; v.y *= g4.y; v.z *= g4.z; v.w *= g4.w;
        __stcs(&xo[t + i * 256], v);
    }
}

extern "C" void kernel_launch(void* const* d_in, const int* in_sizes, int n_in,
                              void* d_out, int out_size) {
    const float* x  = (const float*)d_in[0];
    const float* w1 = (const float*)d_in[1];
    const float* b1 = (const float*)d_in[2];
    const float* w2 = (const float*)d_in[3];
    const float* b2 = (const float*)d_in[4];
    float* out = (float*)d_out;

    se_pool_kernel<<<dim3(NSPLIT, B), 256>>>(x);
    se_gemm1_kernel<<<dim3(R / 128, B), 128>>>(w1, b1);
    se_gemm2_kernel<<<dim3(KSLICES, B), 128>>>(w2);
    se_scale_kernel<<<NSPLIT * B, 256>>>(x, b2, out);
}

// round 5
// speedup vs baseline: 2.6087x; 1.0467x over previous
#include <cuda_runtime.h>
#include <math.h>

// Shapes
// x:  [32, 112, 112, 128] fp32  -> B=32, HW=12544, C=128
// w1: [128, 2048], b1: [2048], w2: [2048, 128], b2: [128]
#define B      32
#define HW     12544
#define C      128
#define R      2048
#define NSPLIT 98
#define ROWS_PER_SPLIT 128
#define F4_PER_B  (HW * C / 4)               // 401408 float4 per batch
#define F4_PER_BLK (ROWS_PER_SPLIT * C / 4)  // 4096 float4 per block
#define RBLKS  (R / 128)                     // 16 excite blocks per batch

// Scratch (device globals: allocation-free)
__device__ __align__(16) float g_partial[B * NSPLIT * C];   // 1.6 MB pool partials
__device__ __align__(16) float g_gp[B * RBLKS * C];         // gate partials, 256 KB

// ---------------------------------------------------------------------------
// Kernel 1: partial pooling sums.  grid (NSPLIT, B), 256 threads.
// Channel group per thread is fixed (256 % 32 == 0), so each thread
// accumulates one float4 of 4 channels across its rows.
// ---------------------------------------------------------------------------
__global__ __launch_bounds__(256, 8)
void se_pool_kernel(const float* __restrict__ x) {
    const int b = blockIdx.y;
    const int split = blockIdx.x;
    const float4* __restrict__ xb =
        reinterpret_cast<const float4*>(x) + (size_t)b * F4_PER_B + (size_t)split * F4_PER_BLK;
    const int t = threadIdx.x;

    float4 acc = make_float4(0.f, 0.f, 0.f, 0.f);
#pragma unroll
    for (int i = 0; i < 16; i++) {           // 16 * 256 = 4096 float4
        float4 v = xb[t + i * 256];
        acc.x += v.x; acc.y += v.y; acc.z += v.z; acc.w += v.w;
    }

    __shared__ float4 sh[256];
    sh[t] = acc;
    __syncthreads();

    if (t < 32) {
        float4 s = sh[t];
#pragma unroll
        for (int j = 1; j < 8; j++) {
            float4 v = sh[t + j * 32];
            s.x += v.x; s.y += v.y; s.z += v.z; s.w += v.w;
        }
        reinterpret_cast<float4*>(g_partial)[(size_t)(b * NSPLIT + split) * 32 + t] = s;
    }
}

// ---------------------------------------------------------------------------
// Kernel 2: fused excite.  grid (RBLKS=16, B), 128 threads.
// Per block (rblk, b):
//   a) redundantly reduce this batch's pool partials (50 KB, L2-hit) -> s[128]
//   b) GEMM1 + tanh-GELU for r in [rblk*128, rblk*128+128) -> h in shared
//   c) GEMM2 partial: gp[c] = sum_{r in chunk} h[r] * w2[r][c]  (h never
//      leaves shared memory; finalize + sigmoid happens in the scale kernel)
// ---------------------------------------------------------------------------
__global__ __launch_bounds__(128, 8)
void se_excite_kernel(const float* __restrict__ w1, const float* __restrict__ b1,
                      const float* __restrict__ w2) {
    const int b = blockIdx.y;
    const int rblk = blockIdx.x;
    const int t = threadIdx.x;

    __shared__ float s[C];
    __shared__ float h[128];

    // a) reduce pool partials -> mean
    {
        const float* p = g_partial + (size_t)b * NSPLIT * C + t;
        float acc = 0.f;
#pragma unroll 14
        for (int k = 0; k < NSPLIT; k++) acc += p[(size_t)k * C];
        s[t] = acc * (1.0f / (float)HW);
    }
    __syncthreads();

    // b) GEMM1 + tanh-approx GELU (one r per thread, coalesced w1 columns)
    {
        const int r = rblk * 128 + t;
        float acc = b1[r];
#pragma unroll 16
        for (int c = 0; c < C; c++) acc += s[c] * w1[(size_t)c * R + r];
        float u = acc;
        float inner = 0.7978845608028654f * (u + 0.044715f * u * u * u);
        h[t] = 0.5f * u * (1.0f + tanhf(inner));
    }
    __syncthreads();

    // c) GEMM2 partial for this r-chunk (one c per thread, coalesced w2 rows)
    {
        const float* w2s = w2 + (size_t)(rblk * 128) * C + t;
        float acc = 0.f;
#pragma unroll 16
        for (int rr = 0; rr < 128; rr++) acc += h[rr] * w2s[(size_t)rr * C];
        g_gp[((size_t)b * RBLKS + rblk) * C + t] = acc;
    }
}

// ---------------------------------------------------------------------------
// Kernel 3: scale with fused gate finalize.  grid (NSPLIT*B), 256 threads.
// Traverses x in REVERSE of pool order so pool's L2-resident tail is hit.
// Output uses streaming stores to avoid evicting that tail.
// ---------------------------------------------------------------------------
__global__ __launch_bounds__(256, 8)
void se_scale_kernel(const float* __restrict__ x, const float* __restrict__ b2,
                     float* __restrict__ out) {
    const int rid = (B * NSPLIT - 1) - blockIdx.x;   // reversed traversal
    const int b   = rid / NSPLIT;
    const int blk = rid % NSPLIT;
    const int t = threadIdx.x;

    // gate for this thread's fixed 4-channel group
    const int c4 = (t * 4) & (C - 1);
    float4 g4;
    {
        float4 a = *reinterpret_cast<const float4*>(b2 + c4);
#pragma unroll
        for (int j = 0; j < RBLKS; j++) {
            float4 p = *reinterpret_cast<const float4*>(g_gp + ((size_t)b * RBLKS + j) * C + c4);
            a.x += p.x; a.y += p.y; a.z += p.z; a.w += p.w;
        }
        g4.x = 1.0f / (1.0f + __expf(-a.x));
        g4.y = 1.0f / (1.0f + __expf(-a.y));
        g4.z = 1.0f / (1.0f + __expf(-a.z));
        g4.w = 1.0f / (1.0f + __expf(-a.w));
    }

    const size_t base = (size_t)b * F4_PER_B + (size_t)blk * F4_PER_BLK;
    const float4* __restrict__ xi = reinterpret_cast<const float4*>(x) + base;
    float4* __restrict__ xo = reinterpret_cast<float4*>(out) + base;

#pragma unroll
    for (int i = 0; i < 16; i++) {
        float4 v = xi[t + i * 256];
        v.x *= g4.x; v.y *= g4.y; v.z *= g4.z; v.w *= g4.w;
        __stcs(&xo[t + i * 256], v);
    }
}

extern "C" void kernel_launch(void* const* d_in, const int* in_sizes, int n_in,
                              void* d_out, int out_size) {
    const float* x  = (const float*)d_in[0];
    const float* w1 = (const float*)d_in[1];
    const float* b1 = (const float*)d_in[2];
    const float* w2 = (const float*)d_in[3];
    const float* b2 = (const float*)d_in[4];
    float* out = (float*)d_out;

    se_pool_kernel<<<dim3(NSPLIT, B), 256>>>(x);
    se_excite_kernel<<<dim3(RBLKS, B), 128>>>(w1, b1, w2);
    se_scale_kernel<<<NSPLIT * B, 256>>>(x, b2, out);
}